// round 15
// baseline (speedup 1.0000x reference)
#include <cuda_runtime.h>
#include <math.h>

#define F      128
#define HEADS  4
#define NMAX   50000
#define GMAX   64
#define EMAX   860000
#define XPAD2  132

// ---------------- device scratch ----------------
__device__ __align__(16) float g_h   [NMAX * F];
__device__ __align__(16) float g_buf [NMAX * F];
__device__ __align__(16) float g_as  [NMAX * HEADS];
__device__ __align__(16) float g_ad  [NMAX * HEADS];
__device__ __align__(16) float g_w   [EMAX * HEADS];
__device__ __align__(16) int  g_deg [NMAX];            // zero-init; scan_k restores zeros
__device__             int   g_rowptr[NMAX + 1];
__device__             int   g_wpos[NMAX];
__device__             int   g_csrc[EMAX];
__device__             int   g_cdst[EMAX];

__device__ __forceinline__ unsigned long long pack_dup(float a) {
    unsigned long long r;
    asm("mov.b64 %0, {%1, %1};" : "=l"(r) : "f"(a));
    return r;
}
__device__ __forceinline__ void fma_f32x2(unsigned long long& d,
                                          unsigned long long a,
                                          unsigned long long b) {
    asm("fma.rn.f32x2 %0, %1, %2, %0;" : "+l"(d) : "l"(a), "l"(b));
}
__device__ __forceinline__ void unpack2(unsigned long long v, float& lo, float& hi) {
    asm("mov.b64 {%0, %1}, %2;" : "=f"(lo), "=f"(hi) : "l"(v));
}

// ---------------- GEMM (f32x2, 128-row tile) + fused alpha ----------------
__global__ void __launch_bounds__(256, 2)
gemm_k(const float* __restrict__ X, const float* __restrict__ W,
       float* __restrict__ O,
       const float* __restrict__ asr, const float* __restrict__ adt,
       int N) {
    extern __shared__ float xs[];          // [128][XPAD2] transposed: xs[k][row]

    const int tid  = threadIdx.x;
    const int row0 = blockIdx.x * 128;

    const float4* X4 = (const float4*)X;
#pragma unroll
    for (int i = 0; i < 16; i++) {
        int idx = tid + i * 256;           // 0..4095
        int r = idx >> 5, kq = idx & 31;
        float4 v = make_float4(0.f, 0.f, 0.f, 0.f);
        int gr = row0 + r;
        if (gr < N) v = X4[gr * 32 + kq];
        xs[(4 * kq + 0) * XPAD2 + r] = v.x;
        xs[(4 * kq + 1) * XPAD2 + r] = v.y;
        xs[(4 * kq + 2) * XPAD2 + r] = v.z;
        xs[(4 * kq + 3) * XPAD2 + r] = v.w;
    }
    __syncthreads();

    const int ty = tid >> 4, tx = tid & 15;   // 8 rows, 8 cols per thread
    unsigned long long acc2[8][4];            // [row][colpair] f32x2
#pragma unroll
    for (int i = 0; i < 8; i++)
#pragma unroll
        for (int j = 0; j < 4; j++) acc2[i][j] = 0ull;

    const ulonglong2* Wp = (const ulonglong2*)W;   // W row: 128 floats = 32 ulonglong2

#pragma unroll 2
    for (int k = 0; k < F; k++) {
        float4 xa = *(const float4*)&xs[k * XPAD2 + ty * 8];
        float4 xb = *(const float4*)&xs[k * XPAD2 + ty * 8 + 4];
        unsigned long long xd[8];
        xd[0] = pack_dup(xa.x); xd[1] = pack_dup(xa.y);
        xd[2] = pack_dup(xa.z); xd[3] = pack_dup(xa.w);
        xd[4] = pack_dup(xb.x); xd[5] = pack_dup(xb.y);
        xd[6] = pack_dup(xb.z); xd[7] = pack_dup(xb.w);
        ulonglong2 wa = __ldg(&Wp[k * 32 + tx * 2]);
        ulonglong2 wb = __ldg(&Wp[k * 32 + tx * 2 + 1]);
        unsigned long long wp[4] = {wa.x, wa.y, wb.x, wb.y};
#pragma unroll
        for (int i = 0; i < 8; i++) {
            fma_f32x2(acc2[i][0], xd[i], wp[0]);
            fma_f32x2(acc2[i][1], xd[i], wp[1]);
            fma_f32x2(acc2[i][2], xd[i], wp[2]);
            fma_f32x2(acc2[i][3], xd[i], wp[3]);
        }
    }

    float4 a0 = *(const float4*)&asr[tx * 8];
    float4 a1 = *(const float4*)&asr[tx * 8 + 4];
    float4 d0 = *(const float4*)&adt[tx * 8];
    float4 d1 = *(const float4*)&adt[tx * 8 + 4];
    float av[8] = {a0.x, a0.y, a0.z, a0.w, a1.x, a1.y, a1.z, a1.w};
    float dv[8] = {d0.x, d0.y, d0.z, d0.w, d1.x, d1.y, d1.z, d1.w};

    const int lane = tid & 31;
    const int head = (lane >> 2) & 3;

#pragma unroll
    for (int i = 0; i < 8; i++) {
        int gr = row0 + ty * 8 + i;
        float acc[8];
#pragma unroll
        for (int j = 0; j < 4; j++)
            unpack2(acc2[i][j], acc[2 * j], acc[2 * j + 1]);
        float ps = 0.f, pd = 0.f;
#pragma unroll
        for (int j = 0; j < 8; j++) {
            ps = fmaf(acc[j], av[j], ps);
            pd = fmaf(acc[j], dv[j], pd);
        }
        ps += __shfl_down_sync(0xffffffffu, ps, 1, 4);
        ps += __shfl_down_sync(0xffffffffu, ps, 2, 4);
        pd += __shfl_down_sync(0xffffffffu, pd, 1, 4);
        pd += __shfl_down_sync(0xffffffffu, pd, 2, 4);
        if (gr < N) {
            if ((lane & 3) == 0) {
                g_as[gr * 4 + head] = ps;
                g_ad[gr * 4 + head] = pd;
            }
            *(float4*)&O[gr * F + tx * 8]     = make_float4(acc[0], acc[1], acc[2], acc[3]);
            *(float4*)&O[gr * F + tx * 8 + 4] = make_float4(acc[4], acc[5], acc[6], acc[7]);
        }
    }
}

// ---------------- CSR build ----------------
__global__ void count_k(const int* __restrict__ ei, int E, int N) {
    int i = blockIdx.x * blockDim.x + threadIdx.x;
    int Et = E + N;
    if (i >= Et) return;
    int dst = (i < E) ? __ldg(&ei[E + i]) : (i - E);
    atomicAdd(&g_deg[dst], 1);
}

__global__ void scan_k(int N) {
    __shared__ int warpsum[32];
    __shared__ int carry_s;
    int tid = threadIdx.x, lane = tid & 31, wid = tid >> 5;
    if (tid == 0) carry_s = 0;
    __syncthreads();
    for (int base = 0; base < N; base += 4096) {
        int i = base + tid * 4;
        int4 v = make_int4(0, 0, 0, 0);
        bool full = (i + 3 < N);
        if (full) v = *(const int4*)&g_deg[i];
        else if (i < N) {
            v.x = g_deg[i];
            if (i + 1 < N) v.y = g_deg[i + 1];
            if (i + 2 < N) v.z = g_deg[i + 2];
        }
        int t1 = v.x + v.y, t2 = t1 + v.z, t3 = t2 + v.w;
        int x = t3;
#pragma unroll
        for (int o = 1; o < 32; o <<= 1) {
            int t = __shfl_up_sync(0xffffffffu, x, o);
            if (lane >= o) x += t;
        }
        if (lane == 31) warpsum[wid] = x;
        __syncthreads();
        if (wid == 0) {
            int s = warpsum[lane];
#pragma unroll
            for (int o = 1; o < 32; o <<= 1) {
                int t = __shfl_up_sync(0xffffffffu, s, o);
                if (lane >= o) s += t;
            }
            warpsum[lane] = s;
        }
        __syncthreads();
        int c    = carry_s;
        int pref = (wid > 0) ? warpsum[wid - 1] : 0;
        int e0 = c + pref + (x - t3);
        if (full) {
            g_rowptr[i] = e0;       g_wpos[i]     = e0;
            g_rowptr[i+1] = e0+v.x; g_wpos[i+1]   = e0+v.x;
            g_rowptr[i+2] = e0+t1;  g_wpos[i+2]   = e0+t1;
            g_rowptr[i+3] = e0+t2;  g_wpos[i+3]   = e0+t2;
            *(int4*)&g_deg[i] = make_int4(0, 0, 0, 0);
        } else if (i < N) {
            g_rowptr[i] = e0; g_wpos[i] = e0; g_deg[i] = 0;
            if (i+1 < N) { g_rowptr[i+1] = e0+v.x; g_wpos[i+1] = e0+v.x; g_deg[i+1] = 0; }
            if (i+2 < N) { g_rowptr[i+2] = e0+t1;  g_wpos[i+2] = e0+t1;  g_deg[i+2] = 0; }
        }
        __syncthreads();
        if (tid == 1023) carry_s = c + pref + x;
        __syncthreads();
    }
    if (threadIdx.x == 0) g_rowptr[N] = carry_s;
}

__global__ void scatter_k(const int* __restrict__ ei, int E, int N) {
    int i = blockIdx.x * blockDim.x + threadIdx.x;
    int Et = E + N;
    if (i >= Et) return;
    int src, dst;
    if (i < E) { src = ei[i]; dst = ei[E + i]; }
    else       { src = dst = i - E; }
    int pos = atomicAdd(&g_wpos[dst], 1);
    g_csrc[pos] = src;
    g_cdst[pos] = dst;
}

// ---------------- edge weight precompute ----------------
__global__ void wk_k(int Et) {
    int i = blockIdx.x * blockDim.x + threadIdx.x;
    if (i >= Et) return;
    int s = g_csrc[i];
    int d = g_cdst[i];
    float4 a = *(const float4*)&g_as[s * 4];
    float4 b = *(const float4*)&g_ad[d * 4];
    float4 w;
    float e;
    e = a.x + b.x; e = e > 0.f ? e : 0.2f * e; w.x = __expf(e);
    e = a.y + b.y; e = e > 0.f ? e : 0.2f * e; w.y = __expf(e);
    e = a.z + b.z; e = e > 0.f ? e : 0.2f * e; w.z = __expf(e);
    e = a.w + b.w; e = e > 0.f ? e : 0.2f * e; w.w = __expf(e);
    *(float4*)&g_w[i * 4] = w;
}

// ---------------- aggregation + bias (+ELU), warp per dst ----------------
__global__ void __launch_bounds__(256)
aggr_k(const float* __restrict__ Hm,
       float* __restrict__ O,
       const float* __restrict__ bias,
       int N, int do_elu) {
    int d    = (blockIdx.x * blockDim.x + threadIdx.x) >> 5;
    int lane = threadIdx.x & 31;
    if (d >= N) return;
    int head = lane >> 3;

    int i0 = g_rowptr[d];
    int i1 = g_rowptr[d + 1];

    float4 acc = make_float4(0.f, 0.f, 0.f, 0.f);
    float sw = 0.f;

    float  w_next  = 0.f;
    float4 hv_next = make_float4(0.f, 0.f, 0.f, 0.f);
    if (i0 < i1) {
        int sn = __ldg(&g_csrc[i0]);
        w_next  = __ldg(&g_w[i0 * 4 + head]);
        hv_next = *(const float4*)&Hm[sn * F + lane * 4];
    }

    for (int i = i0; i < i1; i++) {
        float  w  = w_next;
        float4 hv = hv_next;
        if (i + 1 < i1) {
            int sn = __ldg(&g_csrc[i + 1]);
            w_next  = __ldg(&g_w[(i + 1) * 4 + head]);
            hv_next = *(const float4*)&Hm[sn * F + lane * 4];
        }
        sw += w;
        acc.x = fmaf(w, hv.x, acc.x);
        acc.y = fmaf(w, hv.y, acc.y);
        acc.z = fmaf(w, hv.z, acc.z);
        acc.w = fmaf(w, hv.w, acc.w);
    }

    float inv = 1.0f / (sw + 1e-16f);
    float4 b4 = *(const float4*)&bias[lane * 4];
    float4 o;
    o.x = acc.x * inv + b4.x;
    o.y = acc.y * inv + b4.y;
    o.z = acc.z * inv + b4.z;
    o.w = acc.w * inv + b4.w;
    if (do_elu) {
        o.x = o.x > 0.f ? o.x : expm1f(o.x);
        o.y = o.y > 0.f ? o.y : expm1f(o.y);
        o.z = o.z > 0.f ? o.z : expm1f(o.z);
        o.w = o.w > 0.f ? o.w : expm1f(o.w);
    }
    *(float4*)&O[d * F + lane * 4] = o;
}

// ---------------- pooling + final linear ----------------
__global__ void pool_final_k(const float* __restrict__ B,
                             const int* __restrict__ batch,
                             const float* __restrict__ lw,
                             const float* __restrict__ lb,
                             float* __restrict__ out, int N) {
    int g    = blockIdx.x;
    int tid  = threadIdx.x;       // 0..511
    int c    = tid & 127;
    int part = tid >> 7;

    int lo = 0, hi = N;
    while (lo < hi) { int mid = (lo + hi) >> 1; if (__ldg(&batch[mid]) < g) lo = mid + 1; else hi = mid; }
    int start = lo;
    hi = N;
    while (lo < hi) { int mid = (lo + hi) >> 1; if (__ldg(&batch[mid]) < g + 1) lo = mid + 1; else hi = mid; }
    int end = lo;

    float sum = 0.f, mx = -INFINITY;
    for (int n = start + part; n < end; n += 4) {
        float v = __ldg(&B[n * F + c]);
        sum += v; mx = fmaxf(mx, v);
    }

    __shared__ float s_sum[512];
    __shared__ float s_max[512];
    s_sum[tid] = sum; s_max[tid] = mx;
    __syncthreads();
    if (part == 0) {
        sum = s_sum[c] + s_sum[c + 128] + s_sum[c + 256] + s_sum[c + 384];
        mx  = fmaxf(fmaxf(s_max[c], s_max[c + 128]), fmaxf(s_max[c + 256], s_max[c + 384]));
        float cnt = fmaxf((float)(end - start), 1.0f);
        if (isinf(mx)) mx = 0.f;
        s_sum[c] = (sum / cnt + mx) * __ldg(&lw[c]);
    }
    __syncthreads();
#pragma unroll
    for (int o = 64; o; o >>= 1) {
        if (tid < o) s_sum[tid] += s_sum[tid + o];
        __syncthreads();
    }
    if (tid == 0) out[g] = s_sum[0] + __ldg(&lb[0]);
}

// ---------------- launcher ----------------
extern "C" void kernel_launch(void* const* d_in, const int* in_sizes, int n_in,
                              void* d_out, int out_size) {
    const float* x     = (const float*)d_in[0];
    const int*   ei    = (const int*)d_in[1];
    const int*   batch = (const int*)d_in[2];
    const float* W1    = (const float*)d_in[3];
    const float* as1   = (const float*)d_in[4];
    const float* ad1   = (const float*)d_in[5];
    const float* b1    = (const float*)d_in[6];
    const float* W2    = (const float*)d_in[7];
    const float* as2   = (const float*)d_in[8];
    const float* ad2   = (const float*)d_in[9];
    const float* b2    = (const float*)d_in[10];
    const float* lw    = (const float*)d_in[11];
    const float* lb    = (const float*)d_in[12];

    int N  = in_sizes[0] / F;
    int E  = in_sizes[1] / 2;
    int Et = E + N;

    float *hptr, *bptr;
    cudaGetSymbolAddress((void**)&hptr, g_h);
    cudaGetSymbolAddress((void**)&bptr, g_buf);

    size_t smem = (size_t)(F * XPAD2) * sizeof(float);
    cudaFuncSetAttribute(gemm_k, cudaFuncAttributeMaxDynamicSharedMemorySize, (int)smem);

    int gemm_blocks      = (N + 127) / 128;
    int node_warp_blocks = (N * 32 + 255) / 256;
    int edge_blocks      = (Et + 255) / 256;

    // ---- CSR build ----
    count_k<<<edge_blocks, 256>>>(ei, E, N);
    scan_k<<<1, 1024>>>(N);
    scatter_k<<<edge_blocks, 256>>>(ei, E, N);

    // ---- layer 1 ----
    gemm_k<<<gemm_blocks, 256, smem>>>(x, W1, hptr, as1, ad1, N);   // 4th -> ncu
    wk_k<<<edge_blocks, 256>>>(Et);
    aggr_k<<<node_warp_blocks, 256>>>(hptr, bptr, b1, N, 1);

    // ---- layer 2 ----
    gemm_k<<<gemm_blocks, 256, smem>>>(bptr, W2, hptr, as2, ad2, N);
    wk_k<<<edge_blocks, 256>>>(Et);
    aggr_k<<<node_warp_blocks, 256>>>(hptr, bptr, b2, N, 0);

    // ---- pooling + final linear ----
    pool_final_k<<<GMAX, 512>>>(bptr, batch, lw, lb, (float*)d_out, N);
}

// round 17
// speedup vs baseline: 1.2996x; 1.2996x over previous
#include <cuda_runtime.h>
#include <math.h>
#include <stdint.h>

#define F      128
#define HEADS  4
#define NMAX   50000
#define GMAX   64
#define EMAX   860000
#define SPITCH 132   // X smem pitch (floats)
#define WPITCH 130   // W smem pitch (uint2 hi/lo pairs)

// ---------------- device scratch ----------------
__device__ __align__(16) float g_h   [NMAX * F];
__device__ __align__(16) float g_buf [NMAX * F];
__device__ __align__(16) float g_as  [NMAX * HEADS];
__device__ __align__(16) float g_ad  [NMAX * HEADS];
__device__ __align__(16) float g_w   [EMAX * HEADS];
__device__ __align__(16) int  g_deg [NMAX];            // zero-init; scan_k restores zeros
__device__             int   g_rowptr[NMAX + 1];
__device__             int   g_wpos[NMAX];
__device__             int   g_csrc[EMAX];
__device__             int   g_cdst[EMAX];

__device__ __forceinline__ uint32_t to_tf32(float f) {
    uint32_t u;
    asm("cvt.rna.tf32.f32 %0, %1;" : "=r"(u) : "f"(f));
    return u;
}
__device__ __forceinline__ uint2 split_tf32(float f) {
    uint32_t hi = to_tf32(f);
    uint32_t lo = to_tf32(f - __uint_as_float(hi));
    return make_uint2(hi, lo);
}

__device__ __forceinline__ void mma_tf32(float* c, const uint32_t* a,
                                         uint32_t b0, uint32_t b1) {
    asm volatile(
        "mma.sync.aligned.m16n8k8.row.col.f32.tf32.tf32.f32 "
        "{%0,%1,%2,%3}, {%4,%5,%6,%7}, {%8,%9}, {%0,%1,%2,%3};"
        : "+f"(c[0]), "+f"(c[1]), "+f"(c[2]), "+f"(c[3])
        : "r"(a[0]), "r"(a[1]), "r"(a[2]), "r"(a[3]), "r"(b0), "r"(b1));
}

// ---------------- GEMM (split-tf32 tensor core) + fused alpha ----------------
// Block tile 128x128, 8 warps as 4(M) x 2(N); warp tile m32 x n64.
// X·W ≈ Xh·Wh + Xh·Wl + Xl·Wh  (fp32 accumulate)  -> ~fp32 precision.
__global__ void __launch_bounds__(256, 1)
gemm_k(const float* __restrict__ X, const float* __restrict__ W,
       float* __restrict__ O,
       const float* __restrict__ asr, const float* __restrict__ adt,
       int N) {
    extern __shared__ char sm_raw[];
    float* Xs = (float*)sm_raw;                              // [128][SPITCH] fp32
    uint2* Ws = (uint2*)(sm_raw + 128 * SPITCH * 4);         // [128][WPITCH] (hi,lo)

    const int tid  = threadIdx.x;
    const int row0 = blockIdx.x * 128;

    const float4* X4 = (const float4*)X;
    const float4* W4 = (const float4*)W;
#pragma unroll
    for (int i = 0; i < 16; i++) {
        int idx = tid + i * 256;      // 0..4095 float4 slots
        int r  = idx >> 5;            // row / k-row
        int c4 = idx & 31;            // float4 column
        float4 v = make_float4(0.f, 0.f, 0.f, 0.f);
        if (row0 + r < N) v = X4[(row0 + r) * 32 + c4];
        Xs[r * SPITCH + c4 * 4 + 0] = v.x;
        Xs[r * SPITCH + c4 * 4 + 1] = v.y;
        Xs[r * SPITCH + c4 * 4 + 2] = v.z;
        Xs[r * SPITCH + c4 * 4 + 3] = v.w;
        float4 wv = W4[idx];
        Ws[r * WPITCH + c4 * 4 + 0] = split_tf32(wv.x);
        Ws[r * WPITCH + c4 * 4 + 1] = split_tf32(wv.y);
        Ws[r * WPITCH + c4 * 4 + 2] = split_tf32(wv.z);
        Ws[r * WPITCH + c4 * 4 + 3] = split_tf32(wv.w);
    }
    __syncthreads();

    const int lane = tid & 31;
    const int warp = tid >> 5;
    const int gid  = lane >> 2;   // 0..7
    const int tig  = lane & 3;    // 0..3
    const int mrow = (warp >> 1) * 32;   // 0,32,64,96
    const int ncol = (warp & 1) * 64;    // 0,64

    float c[2][8][4];
#pragma unroll
    for (int i = 0; i < 2; i++)
#pragma unroll
        for (int j = 0; j < 8; j++)
#pragma unroll
            for (int q = 0; q < 4; q++) c[i][j][q] = 0.f;

#pragma unroll
    for (int ks = 0; ks < 16; ks++) {
        int k0 = ks * 8;
        uint32_t ah[2][4], al[2][4];
#pragma unroll
        for (int i = 0; i < 2; i++) {
            int rb = mrow + i * 16;
            float f0 = Xs[(rb + gid)     * SPITCH + k0 + tig];
            float f1 = Xs[(rb + gid + 8) * SPITCH + k0 + tig];
            float f2 = Xs[(rb + gid)     * SPITCH + k0 + tig + 4];
            float f3 = Xs[(rb + gid + 8) * SPITCH + k0 + tig + 4];
            uint2 s0 = split_tf32(f0), s1 = split_tf32(f1);
            uint2 s2 = split_tf32(f2), s3 = split_tf32(f3);
            ah[i][0] = s0.x; al[i][0] = s0.y;
            ah[i][1] = s1.x; al[i][1] = s1.y;
            ah[i][2] = s2.x; al[i][2] = s2.y;
            ah[i][3] = s3.x; al[i][3] = s3.y;
        }
#pragma unroll
        for (int j = 0; j < 8; j++) {
            uint2 b0 = Ws[(k0 + tig)     * WPITCH + ncol + j * 8 + gid];
            uint2 b1 = Ws[(k0 + tig + 4) * WPITCH + ncol + j * 8 + gid];
            mma_tf32(c[0][j], ah[0], b0.x, b1.x);   // Xh·Wh
            mma_tf32(c[0][j], ah[0], b0.y, b1.y);   // Xh·Wl
            mma_tf32(c[0][j], al[0], b0.x, b1.x);   // Xl·Wh
            mma_tf32(c[1][j], ah[1], b0.x, b1.x);
            mma_tf32(c[1][j], ah[1], b0.y, b1.y);
            mma_tf32(c[1][j], al[1], b0.x, b1.x);
        }
    }

    // attention vectors for this thread's 16 columns
    float av[8][2], dv[8][2];
#pragma unroll
    for (int j = 0; j < 8; j++) {
        int col = ncol + j * 8 + 2 * tig;
        float2 t = *(const float2*)&asr[col];
        float2 u = *(const float2*)&adt[col];
        av[j][0] = t.x; av[j][1] = t.y;
        dv[j][0] = u.x; dv[j][1] = u.y;
    }
    const int headA = ncol >> 5;   // this warp owns heads headA, headA+1

#pragma unroll
    for (int i = 0; i < 2; i++) {
#pragma unroll
        for (int rh = 0; rh < 2; rh++) {
            int gr = row0 + mrow + i * 16 + gid + rh * 8;
            float psA = 0.f, pdA = 0.f, psB = 0.f, pdB = 0.f;
#pragma unroll
            for (int j = 0; j < 4; j++) {
                psA += c[i][j][2*rh] * av[j][0] + c[i][j][2*rh+1] * av[j][1];
                pdA += c[i][j][2*rh] * dv[j][0] + c[i][j][2*rh+1] * dv[j][1];
            }
#pragma unroll
            for (int j = 4; j < 8; j++) {
                psB += c[i][j][2*rh] * av[j][0] + c[i][j][2*rh+1] * av[j][1];
                pdB += c[i][j][2*rh] * dv[j][0] + c[i][j][2*rh+1] * dv[j][1];
            }
            psA += __shfl_down_sync(0xffffffffu, psA, 1, 4);
            psA += __shfl_down_sync(0xffffffffu, psA, 2, 4);
            pdA += __shfl_down_sync(0xffffffffu, pdA, 1, 4);
            pdA += __shfl_down_sync(0xffffffffu, pdA, 2, 4);
            psB += __shfl_down_sync(0xffffffffu, psB, 1, 4);
            psB += __shfl_down_sync(0xffffffffu, psB, 2, 4);
            pdB += __shfl_down_sync(0xffffffffu, pdB, 1, 4);
            pdB += __shfl_down_sync(0xffffffffu, pdB, 2, 4);
            if (gr < N) {
                if (tig == 0) {
                    g_as[gr * 4 + headA]     = psA;
                    g_as[gr * 4 + headA + 1] = psB;
                    g_ad[gr * 4 + headA]     = pdA;
                    g_ad[gr * 4 + headA + 1] = pdB;
                }
#pragma unroll
                for (int j = 0; j < 8; j++) {
                    float2 o2 = make_float2(c[i][j][2*rh], c[i][j][2*rh+1]);
                    *(float2*)&O[gr * F + ncol + j * 8 + 2 * tig] = o2;
                }
            }
        }
    }
}

// ---------------- CSR build ----------------
__global__ void count_k(const int* __restrict__ ei, int E, int N) {
    int i = blockIdx.x * blockDim.x + threadIdx.x;
    int Et = E + N;
    if (i >= Et) return;
    int dst = (i < E) ? __ldg(&ei[E + i]) : (i - E);
    atomicAdd(&g_deg[dst], 1);
}

__global__ void scan_k(int N) {
    __shared__ int warpsum[32];
    __shared__ int carry_s;
    int tid = threadIdx.x, lane = tid & 31, wid = tid >> 5;
    if (tid == 0) carry_s = 0;
    __syncthreads();
    for (int base = 0; base < N; base += 4096) {
        int i = base + tid * 4;
        int4 v = make_int4(0, 0, 0, 0);
        bool full = (i + 3 < N);
        if (full) v = *(const int4*)&g_deg[i];
        else if (i < N) {
            v.x = g_deg[i];
            if (i + 1 < N) v.y = g_deg[i + 1];
            if (i + 2 < N) v.z = g_deg[i + 2];
        }
        int t1 = v.x + v.y, t2 = t1 + v.z, t3 = t2 + v.w;
        int x = t3;
#pragma unroll
        for (int o = 1; o < 32; o <<= 1) {
            int t = __shfl_up_sync(0xffffffffu, x, o);
            if (lane >= o) x += t;
        }
        if (lane == 31) warpsum[wid] = x;
        __syncthreads();
        if (wid == 0) {
            int s = warpsum[lane];
#pragma unroll
            for (int o = 1; o < 32; o <<= 1) {
                int t = __shfl_up_sync(0xffffffffu, s, o);
                if (lane >= o) s += t;
            }
            warpsum[lane] = s;
        }
        __syncthreads();
        int cc   = carry_s;
        int pref = (wid > 0) ? warpsum[wid - 1] : 0;
        int e0 = cc + pref + (x - t3);
        if (full) {
            g_rowptr[i] = e0;       g_wpos[i]     = e0;
            g_rowptr[i+1] = e0+v.x; g_wpos[i+1]   = e0+v.x;
            g_rowptr[i+2] = e0+t1;  g_wpos[i+2]   = e0+t1;
            g_rowptr[i+3] = e0+t2;  g_wpos[i+3]   = e0+t2;
            *(int4*)&g_deg[i] = make_int4(0, 0, 0, 0);
        } else if (i < N) {
            g_rowptr[i] = e0; g_wpos[i] = e0; g_deg[i] = 0;
            if (i+1 < N) { g_rowptr[i+1] = e0+v.x; g_wpos[i+1] = e0+v.x; g_deg[i+1] = 0; }
            if (i+2 < N) { g_rowptr[i+2] = e0+t1;  g_wpos[i+2] = e0+t1;  g_deg[i+2] = 0; }
        }
        __syncthreads();
        if (tid == 1023) carry_s = cc + pref + x;
        __syncthreads();
    }
    if (threadIdx.x == 0) g_rowptr[N] = carry_s;
}

__global__ void scatter_k(const int* __restrict__ ei, int E, int N) {
    int i = blockIdx.x * blockDim.x + threadIdx.x;
    int Et = E + N;
    if (i >= Et) return;
    int src, dst;
    if (i < E) { src = ei[i]; dst = ei[E + i]; }
    else       { src = dst = i - E; }
    int pos = atomicAdd(&g_wpos[dst], 1);
    g_csrc[pos] = src;
    g_cdst[pos] = dst;
}

// ---------------- edge weight precompute ----------------
__global__ void wk_k(int Et) {
    int i = blockIdx.x * blockDim.x + threadIdx.x;
    if (i >= Et) return;
    int s = g_csrc[i];
    int d = g_cdst[i];
    float4 a = *(const float4*)&g_as[s * 4];
    float4 b = *(const float4*)&g_ad[d * 4];
    float4 w;
    float e;
    e = a.x + b.x; e = e > 0.f ? e : 0.2f * e; w.x = __expf(e);
    e = a.y + b.y; e = e > 0.f ? e : 0.2f * e; w.y = __expf(e);
    e = a.z + b.z; e = e > 0.f ? e : 0.2f * e; w.z = __expf(e);
    e = a.w + b.w; e = e > 0.f ? e : 0.2f * e; w.w = __expf(e);
    *(float4*)&g_w[i * 4] = w;
}

// ---------------- aggregation + bias (+ELU), warp per dst ----------------
__global__ void __launch_bounds__(256)
aggr_k(const float* __restrict__ Hm,
       float* __restrict__ O,
       const float* __restrict__ bias,
       int N, int do_elu) {
    int d    = (blockIdx.x * blockDim.x + threadIdx.x) >> 5;
    int lane = threadIdx.x & 31;
    if (d >= N) return;
    int head = lane >> 3;

    int i0 = g_rowptr[d];
    int i1 = g_rowptr[d + 1];

    float4 acc = make_float4(0.f, 0.f, 0.f, 0.f);
    float sw = 0.f;

    float  w_next  = 0.f;
    float4 hv_next = make_float4(0.f, 0.f, 0.f, 0.f);
    if (i0 < i1) {
        int sn = __ldg(&g_csrc[i0]);
        w_next  = __ldg(&g_w[i0 * 4 + head]);
        hv_next = *(const float4*)&Hm[sn * F + lane * 4];
    }

    for (int i = i0; i < i1; i++) {
        float  w  = w_next;
        float4 hv = hv_next;
        if (i + 1 < i1) {
            int sn = __ldg(&g_csrc[i + 1]);
            w_next  = __ldg(&g_w[(i + 1) * 4 + head]);
            hv_next = *(const float4*)&Hm[sn * F + lane * 4];
        }
        sw += w;
        acc.x = fmaf(w, hv.x, acc.x);
        acc.y = fmaf(w, hv.y, acc.y);
        acc.z = fmaf(w, hv.z, acc.z);
        acc.w = fmaf(w, hv.w, acc.w);
    }

    float inv = 1.0f / (sw + 1e-16f);
    float4 b4 = *(const float4*)&bias[lane * 4];
    float4 o;
    o.x = acc.x * inv + b4.x;
    o.y = acc.y * inv + b4.y;
    o.z = acc.z * inv + b4.z;
    o.w = acc.w * inv + b4.w;
    if (do_elu) {
        o.x = o.x > 0.f ? o.x : expm1f(o.x);
        o.y = o.y > 0.f ? o.y : expm1f(o.y);
        o.z = o.z > 0.f ? o.z : expm1f(o.z);
        o.w = o.w > 0.f ? o.w : expm1f(o.w);
    }
    *(float4*)&O[d * F + lane * 4] = o;
}

// ---------------- pooling + final linear ----------------
__global__ void pool_final_k(const float* __restrict__ B,
                             const int* __restrict__ batch,
                             const float* __restrict__ lw,
                             const float* __restrict__ lb,
                             float* __restrict__ out, int N) {
    int g    = blockIdx.x;
    int tid  = threadIdx.x;       // 0..511
    int c    = tid & 127;
    int part = tid >> 7;

    int lo = 0, hi = N;
    while (lo < hi) { int mid = (lo + hi) >> 1; if (__ldg(&batch[mid]) < g) lo = mid + 1; else hi = mid; }
    int start = lo;
    hi = N;
    while (lo < hi) { int mid = (lo + hi) >> 1; if (__ldg(&batch[mid]) < g + 1) lo = mid + 1; else hi = mid; }
    int end = lo;

    float sum = 0.f, mx = -INFINITY;
    for (int n = start + part; n < end; n += 4) {
        float v = __ldg(&B[n * F + c]);
        sum += v; mx = fmaxf(mx, v);
    }

    __shared__ float s_sum[512];
    __shared__ float s_max[512];
    s_sum[tid] = sum; s_max[tid] = mx;
    __syncthreads();
    if (part == 0) {
        sum = s_sum[c] + s_sum[c + 128] + s_sum[c + 256] + s_sum[c + 384];
        mx  = fmaxf(fmaxf(s_max[c], s_max[c + 128]), fmaxf(s_max[c + 256], s_max[c + 384]));
        float cnt = fmaxf((float)(end - start), 1.0f);
        if (isinf(mx)) mx = 0.f;
        s_sum[c] = (sum / cnt + mx) * __ldg(&lw[c]);
    }
    __syncthreads();
#pragma unroll
    for (int o = 64; o; o >>= 1) {
        if (tid < o) s_sum[tid] += s_sum[tid + o];
        __syncthreads();
    }
    if (tid == 0) out[g] = s_sum[0] + __ldg(&lb[0]);
}

// ---------------- launcher ----------------
extern "C" void kernel_launch(void* const* d_in, const int* in_sizes, int n_in,
                              void* d_out, int out_size) {
    const float* x     = (const float*)d_in[0];
    const int*   ei    = (const int*)d_in[1];
    const int*   batch = (const int*)d_in[2];
    const float* W1    = (const float*)d_in[3];
    const float* as1   = (const float*)d_in[4];
    const float* ad1   = (const float*)d_in[5];
    const float* b1    = (const float*)d_in[6];
    const float* W2    = (const float*)d_in[7];
    const float* as2   = (const float*)d_in[8];
    const float* ad2   = (const float*)d_in[9];
    const float* b2    = (const float*)d_in[10];
    const float* lw    = (const float*)d_in[11];
    const float* lb    = (const float*)d_in[12];

    int N  = in_sizes[0] / F;
    int E  = in_sizes[1] / 2;
    int Et = E + N;

    float *hptr, *bptr;
    cudaGetSymbolAddress((void**)&hptr, g_h);
    cudaGetSymbolAddress((void**)&bptr, g_buf);

    size_t smem = (size_t)128 * SPITCH * 4 + (size_t)128 * WPITCH * 8;   // 200704 B
    cudaFuncSetAttribute(gemm_k, cudaFuncAttributeMaxDynamicSharedMemorySize, (int)smem);

    int gemm_blocks      = (N + 127) / 128;
    int node_warp_blocks = (N * 32 + 255) / 256;
    int edge_blocks      = (Et + 255) / 256;

    // ---- CSR build ----
    count_k<<<edge_blocks, 256>>>(ei, E, N);
    scan_k<<<1, 1024>>>(N);
    scatter_k<<<edge_blocks, 256>>>(ei, E, N);

    // ---- layer 1 ----
    gemm_k<<<gemm_blocks, 256, smem>>>(x, W1, hptr, as1, ad1, N);   // 4th -> ncu
    wk_k<<<edge_blocks, 256>>>(Et);
    aggr_k<<<node_warp_blocks, 256>>>(hptr, bptr, b1, N, 1);

    // ---- layer 2 ----
    gemm_k<<<gemm_blocks, 256, smem>>>(bptr, W2, hptr, as2, ad2, N);
    wk_k<<<edge_blocks, 256>>>(Et);
    aggr_k<<<node_warp_blocks, 256>>>(hptr, bptr, b2, N, 0);

    // ---- pooling + final linear ----
    pool_final_k<<<GMAX, 512>>>(bptr, batch, lw, lb, (float*)d_out, N);
}